// round 16
// baseline (speedup 1.0000x reference)
#include <cuda_runtime.h>
#include <cuda_bf16.h>

// Causal cumulative normalization along frames.
// TWO consecutive rows per warp, 256-frame chunks with 256-bit (v8.f32)
// global loads/stores (one lane = 8 contiguous frames, ONE scan ladder per
// 256 frames), 1-chunk software prefetch. 2048 blocks x 128 thr, 8 blocks/SM.
// Trailing 160 frames handled after the main loop (no persistent buffers,
// keeps the kernel at 64 regs -> 32 warps/SM).
// Division-free: out = (x*c - s) * rsqrt(c*(q + eps*c) - s*s).

#define EPSV 1e-4f

constexpr int FRAMES   = 4000;
constexpr int NFULL256 = 15;   // 15*256 = 3840; then 128-frame chunk; then 32 tail

struct f8 { float v[8]; };

__device__ __forceinline__ f8 ldg256cs(const float* p) {
    f8 r;
    asm volatile("ld.global.cs.v8.f32 {%0,%1,%2,%3,%4,%5,%6,%7}, [%8];"
                 : "=f"(r.v[0]), "=f"(r.v[1]), "=f"(r.v[2]), "=f"(r.v[3]),
                   "=f"(r.v[4]), "=f"(r.v[5]), "=f"(r.v[6]), "=f"(r.v[7])
                 : "l"(p));
    return r;
}

__device__ __forceinline__ void stg256cs(float* p, const f8& r) {
    asm volatile("st.global.cs.v8.f32 [%0], {%1,%2,%3,%4,%5,%6,%7,%8};"
                 :: "l"(p),
                    "f"(r.v[0]), "f"(r.v[1]), "f"(r.v[2]), "f"(r.v[3]),
                    "f"(r.v[4]), "f"(r.v[5]), "f"(r.v[6]), "f"(r.v[7])
                 : "memory");
}

// 256 frames per warp: lane covers 8 contiguous frames, one scan ladder.
__device__ __forceinline__ void process256(const f8& cv, float cbase, int lane,
                                           float& carry_s, float& carry_q,
                                           float* outp) {
    float s[8], q[8];
    s[0] = cv.v[0];
    q[0] = cv.v[0] * cv.v[0];
    #pragma unroll
    for (int i = 1; i < 8; ++i) {
        s[i] = s[i - 1] + cv.v[i];
        q[i] = fmaf(cv.v[i], cv.v[i], q[i - 1]);
    }

    float ts = s[7], tq = q[7];
    #pragma unroll
    for (int off = 1; off < 32; off <<= 1) {
        float as = __shfl_up_sync(0xffffffffu, ts, off);
        float aq = __shfl_up_sync(0xffffffffu, tq, off);
        if (lane >= off) { ts += as; tq += aq; }
    }

    float bs = carry_s + (ts - s[7]);   // exclusive lane base + carry
    float bq = carry_q + (tq - q[7]);
    carry_s += __shfl_sync(0xffffffffu, ts, 31);
    carry_q += __shfl_sync(0xffffffffu, tq, 31);

    f8 o;
    #pragma unroll
    for (int i = 0; i < 8; ++i) {
        float c  = cbase + (float)i;
        float ss = bs + s[i];
        float qq = bq + q[i];
        float u  = fmaf(EPSV, c, qq);
        float r  = fmaf(c, u, -ss * ss);
        o.v[i]   = fmaf(cv.v[i], c, -ss) * rsqrtf(r);
    }
    stg256cs(outp, o);
}

// trailing 160 frames of one row: 128-frame float4 chunk + 32-frame scalar tail
__device__ __forceinline__ void remainder160(const float* xr, float* outr, int lane,
                                             float carry_s, float carry_q) {
    // frames 3840..3967, float4 per lane
    {
        float4 cv = __ldcs((const float4*)(xr + 3840) + lane);
        float s0 = cv.x;
        float s1 = s0 + cv.y;
        float s2 = s1 + cv.z;
        float s3 = s2 + cv.w;
        float q0 = cv.x * cv.x;
        float q1 = fmaf(cv.y, cv.y, q0);
        float q2 = fmaf(cv.z, cv.z, q1);
        float q3 = fmaf(cv.w, cv.w, q2);

        float ts = s3, tq = q3;
        #pragma unroll
        for (int off = 1; off < 32; off <<= 1) {
            float as = __shfl_up_sync(0xffffffffu, ts, off);
            float aq = __shfl_up_sync(0xffffffffu, tq, off);
            if (lane >= off) { ts += as; tq += aq; }
        }

        float bs = carry_s + (ts - s3);
        float bq = carry_q + (tq - q3);
        carry_s += __shfl_sync(0xffffffffu, ts, 31);
        carry_q += __shfl_sync(0xffffffffu, tq, 31);

        float cb = 3840.0f + (float)(lane * 4 + 1);
        float4 o;
        {
            float c = cb;
            float s = bs + s0, q = bq + q0;
            float u = fmaf(EPSV, c, q);
            float r = fmaf(c, u, -s * s);
            o.x = fmaf(cv.x, c, -s) * rsqrtf(r);
        }
        {
            float c = cb + 1.0f;
            float s = bs + s1, q = bq + q1;
            float u = fmaf(EPSV, c, q);
            float r = fmaf(c, u, -s * s);
            o.y = fmaf(cv.y, c, -s) * rsqrtf(r);
        }
        {
            float c = cb + 2.0f;
            float s = bs + s2, q = bq + q2;
            float u = fmaf(EPSV, c, q);
            float r = fmaf(c, u, -s * s);
            o.z = fmaf(cv.z, c, -s) * rsqrtf(r);
        }
        {
            float c = cb + 3.0f;
            float s = bs + s3, q = bq + q3;
            float u = fmaf(EPSV, c, q);
            float r = fmaf(c, u, -s * s);
            o.w = fmaf(cv.w, c, -s) * rsqrtf(r);
        }
        __stcs((float4*)(outr + 3840) + lane, o);
    }

    // frames 3968..3999, one scalar per lane
    {
        int base = 3968 + lane;
        float xval = __ldcs(xr + base);
        float ts = xval, tq = xval * xval;
        #pragma unroll
        for (int off = 1; off < 32; off <<= 1) {
            float as = __shfl_up_sync(0xffffffffu, ts, off);
            float aq = __shfl_up_sync(0xffffffffu, tq, off);
            if (lane >= off) { ts += as; tq += aq; }
        }
        float c = (float)(base + 1);
        float s = carry_s + ts;
        float q = carry_q + tq;
        float u = fmaf(EPSV, c, q);
        float r = fmaf(c, u, -s * s);
        __stcs(outr + base, fmaf(xval, c, -s) * rsqrtf(r));
    }
}

__global__ __launch_bounds__(128, 8)
void cumnorm_kernel(const float* __restrict__ x, float* __restrict__ out, int pairs) {
    int gw   = (blockIdx.x * blockDim.x + threadIdx.x) >> 5;
    int lane = threadIdx.x & 31;
    if (gw >= pairs) return;

    const float* __restrict__ xs = x   + (long long)(2 * gw) * FRAMES;
    float*       __restrict__ os = out + (long long)(2 * gw) * FRAMES;

    float csa = 0.0f, cqa = 0.0f;   // carries row A
    float csb = 0.0f, cqb = 0.0f;   // carries row B

    float clane = (float)(lane * 8 + 1);
    int loff = lane * 8;

    // prefetch first 256-frame chunk of both rows
    f8 a = ldg256cs(xs + loff);
    f8 b = ldg256cs(xs + FRAMES + loff);

    #pragma unroll 1
    for (int it = 0; it < NFULL256; ++it) {
        f8 ca = a, cb = b;
        if (it + 1 < NFULL256) {
            int nb = (it + 1) * 256 + loff;
            a = ldg256cs(xs + nb);
            b = ldg256cs(xs + FRAMES + nb);
        }
        float cbase = (float)(it * 256) + clane;
        int ob = it * 256 + loff;
        process256(ca, cbase, lane, csa, cqa, os + ob);
        process256(cb, cbase, lane, csb, cqb, os + FRAMES + ob);
    }

    // trailing 160 frames of each row
    remainder160(xs,          os,          lane, csa, cqa);
    remainder160(xs + FRAMES, os + FRAMES, lane, csb, cqb);
}

extern "C" void kernel_launch(void* const* d_in, const int* in_sizes, int n_in,
                              void* d_out, int out_size) {
    const float* x = (const float*)d_in[0];
    float* out = (float*)d_out;
    int rows  = in_sizes[0] / FRAMES;   // 32*512 = 16384
    int pairs = rows / 2;               // 8192

    constexpr int WARPS_PER_BLOCK = 4;  // 128-thread blocks -> 2048 blocks
    int blocks = (pairs + WARPS_PER_BLOCK - 1) / WARPS_PER_BLOCK;
    cumnorm_kernel<<<blocks, WARPS_PER_BLOCK * 32>>>(x, out, pairs);
}